// round 3
// baseline (speedup 1.0000x reference)
#include <cuda_runtime.h>
#include <math.h>
#include <stdint.h>

#define BB 128
#define LL 100
#define HID 256
#define IND 160
#define NCAP 1600
#define CAPD 16
#define NCLS 19
#define ODIM 304

// ---------------- device scratch ----------------
__device__ float g_emb [BB*LL*IND];
__device__ float g_xgf [BB*LL*1024];
__device__ float g_xgb [BB*LL*1024];
__device__ float g_xf  [BB*LL*HID];
__device__ float g_xb  [BB*LL*HID];
__device__ float g_x   [BB*LL*HID];
__device__ float g_att [BB*LL];
__device__ float g_u   [BB*NCAP*CAPD];
__device__ float g_uhat[(size_t)BB*NCAP*ODIM];
__device__ float g_bb  [(size_t)BB*NCAP*NCLS];
__device__ float g_s   [BB*ODIM];
__device__ float g_v   [BB*ODIM];
__device__ float g_dummy;

// ---------------- packed fp32x2 FMA ----------------
__device__ __forceinline__ float2 ffma2(float2 a, float2 b, float2 c) {
    float2 d;
    asm("fma.rn.f32x2 %0, %1, %2, %3;"
        : "=l"(reinterpret_cast<unsigned long long&>(d))
        : "l"(reinterpret_cast<unsigned long long&>(a)),
          "l"(reinterpret_cast<unsigned long long&>(b)),
          "l"(reinterpret_cast<unsigned long long&>(c)));
    return d;
}

__device__ __forceinline__ uint32_t smem_u32(const void* p) {
    uint32_t a;
    asm("{ .reg .u64 t; cvta.to.shared.u64 t, %1; cvt.u32.u64 %0, t; }"
        : "=r"(a) : "l"(p));
    return a;
}

// ---------------- K1: embedding gather ----------------
__global__ void embed_kernel(const int* __restrict__ word, const int* __restrict__ tag,
                             const int* __restrict__ p1,   const int* __restrict__ p2,
                             const float* __restrict__ we, const float* __restrict__ te,
                             const float* __restrict__ p1e,const float* __restrict__ p2e) {
    int idx = blockIdx.x * blockDim.x + threadIdx.x;
    if (idx >= BB*LL*IND) return;
    int bl = idx / IND;
    int d  = idx - bl * IND;
    float v;
    if (d < 100)      v = we[(size_t)word[bl]*100 + d];
    else if (d < 120) v = te[tag[bl]*20 + (d-100)];
    else if (d < 140) v = p1e[p1[bl]*20 + (d-120)];
    else              v = p2e[p2[bl]*20 + (d-140)];
    g_emb[idx] = v;
}

// ---------------- K2: xg GEMM (R1 form, known-good) ----------------
__global__ void __launch_bounds__(256) gemm_xg_kernel(
        const float* __restrict__ wf, const float* __restrict__ wbk,
        const float* __restrict__ bif, const float* __restrict__ bhf,
        const float* __restrict__ bib, const float* __restrict__ bhb) {
    __shared__ float As[16][64];
    __shared__ float Ws[16][64];
    int dir = blockIdx.z;
    const float* W  = dir ? wbk : wf;
    const float* bi = dir ? bib : bif;
    const float* bh = dir ? bhb : bhf;
    float* C = dir ? g_xgb : g_xgf;
    int n0 = blockIdx.x * 64;
    int m0 = blockIdx.y * 64;
    int tid = threadIdx.x;
    int tx = tid & 15, ty = tid >> 4;
    int lrow = tid >> 2, lq = tid & 3;
    float acc[4][4] = {};
    for (int k0 = 0; k0 < 160; k0 += 16) {
        float4 av = *(const float4*)(g_emb + (size_t)(m0 + lrow) * 160 + k0 + lq * 4);
        float4 wv = *(const float4*)(W     + (size_t)(n0 + lrow) * 160 + k0 + lq * 4);
        As[lq*4+0][lrow] = av.x; As[lq*4+1][lrow] = av.y;
        As[lq*4+2][lrow] = av.z; As[lq*4+3][lrow] = av.w;
        Ws[lq*4+0][lrow] = wv.x; Ws[lq*4+1][lrow] = wv.y;
        Ws[lq*4+2][lrow] = wv.z; Ws[lq*4+3][lrow] = wv.w;
        __syncthreads();
        #pragma unroll
        for (int kk = 0; kk < 16; ++kk) {
            float a[4], w[4];
            #pragma unroll
            for (int e = 0; e < 4; ++e) { a[e] = As[kk][ty*4+e]; w[e] = Ws[kk][tx*4+e]; }
            #pragma unroll
            for (int i = 0; i < 4; ++i)
                #pragma unroll
                for (int j = 0; j < 4; ++j)
                    acc[i][j] += a[i] * w[j];
        }
        __syncthreads();
    }
    #pragma unroll
    for (int i = 0; i < 4; ++i) {
        int m = m0 + ty*4 + i;
        #pragma unroll
        for (int j = 0; j < 4; ++j) {
            int n = n0 + tx*4 + j;
            C[(size_t)m * 1024 + n] = acc[i][j] + bi[n] + bh[n];
        }
    }
}

// ---------------- dummy (shifts ncu capture slot onto lstm) ----------------
__global__ void dummy_kernel() {
    if (threadIdx.x == 0) g_dummy = 0.f;
}

// ---------------- K3: cluster-DSMEM BiLSTM ----------------
// 16 clusters of 8 CTAs. Cluster = (dir, b-tile of 16). CTA rank = u-slice of 32.
// w_hh slice (128 rows x 256) in SMEM for all 100 steps. Per step: compute gates
// from assembled h_s, publish h piece to double-buffered hpub, ONE cluster.sync,
// assemble next h_s by DSMEM-reading all 8 ranks' hpub. No global barriers.
#define W_STRIDE 260
#define H_STRIDE 260
#define W_FLOATS (128*W_STRIDE)
#define H_FLOATS (16*H_STRIDE)
#define HPUB_FLOATS (16*32)
#define LSTM_SMEM ((W_FLOATS + H_FLOATS + 2*HPUB_FLOATS + 16) * 4)

__global__ void __launch_bounds__(512, 1) __cluster_dims__(8, 1, 1)
lstm_kernel(const float* __restrict__ whh_f, const float* __restrict__ whh_b) {
    extern __shared__ float sm[];
    float* w_s  = sm;                          // [128][W_STRIDE]
    float* h_s  = sm + W_FLOATS;               // [16][H_STRIDE]
    float* hpub = sm + W_FLOATS + H_FLOATS;    // [2][16][32]

    int cid  = blockIdx.x >> 3;   // 0..15
    int rank = blockIdx.x & 7;    // cluster rank = u-slice
    int dir  = cid >> 3;
    int bt   = cid & 7;
    int b0   = bt * 16;
    int u0   = rank * 32;
    int tid  = threadIdx.x;
    int b_local = (tid & 7) | ((tid >> 5) & 8);   // bits 0-2 + bit 8
    int u_local = (tid >> 3) & 31;
    int b = b0 + b_local;
    int u = u0 + u_local;

    const float* whh = dir ? whh_b : whh_f;
    const float* xg  = dir ? g_xgb : g_xgf;
    float* xout      = dir ? g_xb  : g_xf;

    // load w_hh slice: rows g*256 + u0 + ul, g in 0..3, ul in 0..31
    for (int x = tid; x < 128*64; x += 512) {
        int row = x >> 6;          // 0..127 = g*32+ul
        int q   = x & 63;
        int g = row >> 5, ul = row & 31;
        int R = g*256 + u0 + ul;
        float4 v = *(const float4*)(whh + (size_t)R*256 + q*4);
        *(float4*)(w_s + row*W_STRIDE + q*4) = v;
    }
    for (int x = tid; x < H_FLOATS; x += 512) h_s[x] = 0.f;
    __syncthreads();

    const float4* w0 = (const float4*)(w_s + (0*32 + u_local)*W_STRIDE);
    const float4* w1 = (const float4*)(w_s + (1*32 + u_local)*W_STRIDE);
    const float4* w2 = (const float4*)(w_s + (2*32 + u_local)*W_STRIDE);
    const float4* w3 = (const float4*)(w_s + (3*32 + u_local)*W_STRIDE);
    const float4* hv = (const float4*)(h_s + b_local*H_STRIDE);

    uint32_t hpub_u32 = smem_u32(hpub);
    // assemble-thread mapping (fixed per thread)
    int rr = (tid >> 3) & 7;      // source rank
    int qq = tid & 7;             // float4-within-row
    int bq = tid >> 6;            // 0..7 (handles b=bq and b=bq+8)

    float c_reg = 0.f;
    int parity = 0;

    for (int step = 0; step < LL; ++step) {
        int t = dir ? (LL-1-step) : step;
        const float* xgp = xg + ((size_t)(b*LL + t))*1024 + u;
        float2 acc0 = make_float2(0.f,0.f), acc1 = make_float2(0.f,0.f);
        float2 acc2 = make_float2(0.f,0.f), acc3 = make_float2(0.f,0.f);
        #pragma unroll 4
        for (int k = 0; k < 64; ++k) {
            float4 h4 = hv[k];
            float2 hA = make_float2(h4.x, h4.y);
            float2 hB = make_float2(h4.z, h4.w);
            float4 a;
            a = w0[k]; acc0 = ffma2(hA, make_float2(a.x,a.y), acc0); acc0 = ffma2(hB, make_float2(a.z,a.w), acc0);
            a = w1[k]; acc1 = ffma2(hA, make_float2(a.x,a.y), acc1); acc1 = ffma2(hB, make_float2(a.z,a.w), acc1);
            a = w2[k]; acc2 = ffma2(hA, make_float2(a.x,a.y), acc2); acc2 = ffma2(hB, make_float2(a.z,a.w), acc2);
            a = w3[k]; acc3 = ffma2(hA, make_float2(a.x,a.y), acc3); acc3 = ffma2(hB, make_float2(a.z,a.w), acc3);
        }
        float gi = xgp[0]   + acc0.x + acc0.y;
        float gf = xgp[256] + acc1.x + acc1.y;
        float gg = xgp[512] + acc2.x + acc2.y;
        float go = xgp[768] + acc3.x + acc3.y;
        float ig = 1.f / (1.f + expf(-gi));
        float fg = 1.f / (1.f + expf(-gf));
        float gt = tanhf(gg);
        float og = 1.f / (1.f + expf(-go));
        c_reg = fg * c_reg + ig * gt;
        float h = og * tanhf(c_reg);
        xout[((size_t)(b*LL + t))*HID + u] = h;

        // publish h piece
        hpub[parity*HPUB_FLOATS + b_local*32 + u_local] = h;

        // one cluster barrier: all publishes visible, all CTA threads past compute
        asm volatile("barrier.cluster.arrive.aligned;" ::: "memory");
        asm volatile("barrier.cluster.wait.aligned;"   ::: "memory");

        // assemble h_s[b][rank*32 + :] from each rank's hpub via DSMEM
        #pragma unroll
        for (int half = 0; half < 2; ++half) {
            int bb2 = bq + half*8;
            uint32_t laddr = hpub_u32 + (uint32_t)(parity*HPUB_FLOATS + bb2*32 + qq*4) * 4u;
            uint32_t raddr;
            asm("mapa.shared::cluster.u32 %0, %1, %2;" : "=r"(raddr) : "r"(laddr), "r"(rr));
            unsigned long long lo, hi;
            asm volatile("ld.shared::cluster.b64 %0, [%1];" : "=l"(lo) : "r"(raddr));
            asm volatile("ld.shared::cluster.b64 %0, [%1];" : "=l"(hi) : "r"(raddr + 8u));
            float2 f0 = *(float2*)&lo;
            float2 f1 = *(float2*)&hi;
            *(float4*)(h_s + bb2*H_STRIDE + rr*32 + qq*4) = make_float4(f0.x, f0.y, f1.x, f1.y);
        }
        __syncthreads();
        parity ^= 1;
    }
}

// ---------------- K4: x = hf + hb ----------------
__global__ void addx_kernel() {
    int idx = blockIdx.x * blockDim.x + threadIdx.x;
    if (idx < BB*LL*HID) g_x[idx] = g_xf[idx] + g_xb[idx];
}

// ---------------- K5: entity gather + attention softmax ----------------
__global__ void entity_att_kernel(const int* __restrict__ pos1, const int* __restrict__ pos2) {
    int b = blockIdx.x;
    int tid = threadIdx.x;
    __shared__ int e1s, e2s;
    __shared__ float he_s[256];
    __shared__ float lg[100];
    __shared__ float mred, sred;
    if (tid < 100) {
        if (pos1[b*100 + tid] == 68) e1s = tid;
        if (pos2[b*100 + tid] == 68) e2s = tid;
    }
    __syncthreads();
    for (int u = tid; u < 256; u += 128)
        he_s[u] = g_x[(size_t)(b*100 + e1s)*256 + u] + g_x[(size_t)(b*100 + e2s)*256 + u];
    __syncthreads();
    int w = tid >> 5, lane = tid & 31;
    for (int l = w; l < 100; l += 4) {
        float s = 0.f;
        const float* xp = g_x + (size_t)(b*100 + l)*256;
        for (int u = lane; u < 256; u += 32) s += xp[u] * he_s[u];
        #pragma unroll
        for (int off = 16; off; off >>= 1) s += __shfl_xor_sync(0xffffffffu, s, off);
        if (lane == 0) lg[l] = s;
    }
    __syncthreads();
    if (tid == 0) {
        float m = -1e30f;
        for (int l = 0; l < 100; ++l) m = fmaxf(m, lg[l]);
        float ssum = 0.f;
        for (int l = 0; l < 100; ++l) ssum += expf(lg[l] - m);
        mred = m; sred = ssum;
    }
    __syncthreads();
    if (tid < 100) g_att[b*100 + tid] = expf(lg[tid] - mred) / sred;
}

// ---------------- K6: primary capsule squash ----------------
__global__ void usq_kernel() {
    int idx = blockIdx.x * blockDim.x + threadIdx.x;
    if (idx >= BB*NCAP) return;
    const float* xp = g_x + (size_t)idx * 16;
    float4 a0 = *(const float4*)(xp + 0);
    float4 a1 = *(const float4*)(xp + 4);
    float4 a2 = *(const float4*)(xp + 8);
    float4 a3 = *(const float4*)(xp + 12);
    float n2 = a0.x*a0.x + a0.y*a0.y + a0.z*a0.z + a0.w*a0.w
             + a1.x*a1.x + a1.y*a1.y + a1.z*a1.z + a1.w*a1.w
             + a2.x*a2.x + a2.y*a2.y + a2.z*a2.z + a2.w*a2.w
             + a3.x*a3.x + a3.y*a3.y + a3.z*a3.z + a3.w*a3.w;
    float sc = (n2 / (1.f + n2)) * rsqrtf(n2 + 1e-9f);
    float* up = g_u + (size_t)idx * 16;
    a0.x*=sc; a0.y*=sc; a0.z*=sc; a0.w*=sc;
    a1.x*=sc; a1.y*=sc; a1.z*=sc; a1.w*=sc;
    a2.x*=sc; a2.y*=sc; a2.z*=sc; a2.w*=sc;
    a3.x*=sc; a3.y*=sc; a3.z*=sc; a3.w*=sc;
    *(float4*)(up + 0)  = a0; *(float4*)(up + 4)  = a1;
    *(float4*)(up + 8)  = a2; *(float4*)(up + 12) = a3;
}

// ---------------- K7: u_hat ----------------
__global__ void __launch_bounds__(256) uhat_kernel(const float* __restrict__ Wc) {
    __shared__ float Wsm[16*304];
    __shared__ float Usm[128*16];
    int i = blockIdx.x;
    int tid = threadIdx.x;
    const float* Wp = Wc + (size_t)i * 16 * 304;
    for (int x = tid; x < 16*304; x += 256) Wsm[x] = Wp[x];
    for (int x = tid; x < 128*16; x += 256) {
        int b = x >> 4, c = x & 15;
        Usm[x] = g_u[(size_t)b*25600 + i*16 + c];
    }
    __syncthreads();
    for (int out = tid; out < 128*304; out += 256) {
        int b = out / 304;
        int od = out - b*304;
        float acc = 0.f;
        #pragma unroll
        for (int c = 0; c < 16; ++c) acc += Usm[b*16 + c] * Wsm[c*304 + od];
        g_uhat[((size_t)b*NCAP + i)*ODIM + od] = acc;
    }
}

// ---------------- K8: routing pass (R1 form, known-good) ----------------
__global__ void __launch_bounds__(320) route_kernel(int first, const float* __restrict__ broute) {
    __shared__ float v_s[304], uh_s[304], sacc[304], c_s[19];
    int b = blockIdx.x >> 3;
    int chunk = blockIdx.x & 7;
    int tid = threadIdx.x;
    if (tid < 304) { v_s[tid] = g_v[b*ODIM + tid]; sacc[tid] = 0.f; }
    __syncthreads();
    int i_end = chunk*200 + 200;
    for (int i = chunk*200; i < i_end; ++i) {
        if (tid < 304) uh_s[tid] = g_uhat[((size_t)b*NCAP + i)*ODIM + tid];
        __syncthreads();
        float p = (tid < 304) ? uh_s[tid] * v_s[tid] : 0.f;
        p += __shfl_xor_sync(0xffffffffu, p, 8);
        p += __shfl_xor_sync(0xffffffffu, p, 4);
        p += __shfl_xor_sync(0xffffffffu, p, 2);
        p += __shfl_xor_sync(0xffffffffu, p, 1);
        if (tid < 304 && (tid & 15) == 0) {
            int o = tid >> 4;
            float bbv = (first ? broute[i*NCLS + o]
                               : g_bb[((size_t)b*NCAP + i)*NCLS + o]) + p;
            g_bb[((size_t)b*NCAP + i)*NCLS + o] = bbv;
            c_s[o] = bbv;
        }
        __syncthreads();
        if (tid < 32) {
            float m = (tid < 19) ? c_s[tid] : -1e30f;
            #pragma unroll
            for (int off = 16; off; off >>= 1) m = fmaxf(m, __shfl_xor_sync(0xffffffffu, m, off));
            float e = (tid < 19) ? expf(c_s[tid] - m) : 0.f;
            float ssum = e;
            #pragma unroll
            for (int off = 16; off; off >>= 1) ssum += __shfl_xor_sync(0xffffffffu, ssum, off);
            if (tid < 19) c_s[tid] = (e / ssum) * g_att[b*100 + (i >> 4)];
        }
        __syncthreads();
        if (tid < 304) sacc[tid] += c_s[tid >> 4] * uh_s[tid];
        __syncthreads();
    }
    if (tid < 304) atomicAdd(&g_s[b*ODIM + tid], sacc[tid]);
}

// ---------------- K9: v = squash(s), final lengths ----------------
__global__ void squash_v_kernel(float* __restrict__ out, int last) {
    int idx = blockIdx.x * blockDim.x + threadIdx.x;
    if (idx >= BB*NCLS) return;
    const float* sp = g_s + (size_t)idx * 16;
    float4 a0 = *(const float4*)(sp + 0);
    float4 a1 = *(const float4*)(sp + 4);
    float4 a2 = *(const float4*)(sp + 8);
    float4 a3 = *(const float4*)(sp + 12);
    float n2 = a0.x*a0.x + a0.y*a0.y + a0.z*a0.z + a0.w*a0.w
             + a1.x*a1.x + a1.y*a1.y + a1.z*a1.z + a1.w*a1.w
             + a2.x*a2.x + a2.y*a2.y + a2.z*a2.z + a2.w*a2.w
             + a3.x*a3.x + a3.y*a3.y + a3.z*a3.z + a3.w*a3.w;
    float sc = (n2 / (1.f + n2)) * rsqrtf(n2 + 1e-9f);
    float* vp = g_v + (size_t)idx * 16;
    a0.x*=sc; a0.y*=sc; a0.z*=sc; a0.w*=sc;
    a1.x*=sc; a1.y*=sc; a1.z*=sc; a1.w*=sc;
    a2.x*=sc; a2.y*=sc; a2.z*=sc; a2.w*=sc;
    a3.x*=sc; a3.y*=sc; a3.z*=sc; a3.w*=sc;
    *(float4*)(vp + 0)  = a0; *(float4*)(vp + 4)  = a1;
    *(float4*)(vp + 8)  = a2; *(float4*)(vp + 12) = a3;
    if (last) out[idx] = sqrtf(n2 * sc * sc + 1e-9f);
}

// ---------------- launch ----------------
extern "C" void kernel_launch(void* const* d_in, const int* in_sizes, int n_in,
                              void* d_out, int out_size) {
    const int*   word   = (const int*)d_in[0];
    const int*   tag    = (const int*)d_in[1];
    const int*   pos1   = (const int*)d_in[2];
    const int*   pos2   = (const int*)d_in[3];
    const float* we     = (const float*)d_in[4];
    const float* te     = (const float*)d_in[5];
    const float* p1e    = (const float*)d_in[6];
    const float* p2e    = (const float*)d_in[7];
    const float* wihf   = (const float*)d_in[8];
    const float* whhf   = (const float*)d_in[9];
    const float* bihf   = (const float*)d_in[10];
    const float* bhhf   = (const float*)d_in[11];
    const float* wihb   = (const float*)d_in[12];
    const float* whhb   = (const float*)d_in[13];
    const float* bihb   = (const float*)d_in[14];
    const float* bhhb   = (const float*)d_in[15];
    const float* wcaps  = (const float*)d_in[16];
    const float* broute = (const float*)d_in[17];
    float* out = (float*)d_out;

    cudaFuncSetAttribute(lstm_kernel, cudaFuncAttributeMaxDynamicSharedMemorySize, LSTM_SMEM);

    embed_kernel<<<(BB*LL*IND + 255)/256, 256>>>(word, tag, pos1, pos2, we, te, p1e, p2e);   // launch 1

    dim3 gg(16, 200, 2);
    gemm_xg_kernel<<<gg, 256>>>(wihf, wihb, bihf, bhhf, bihb, bhhb);                          // launch 2

    dummy_kernel<<<1, 32>>>();                                                                 // launch 3

    lstm_kernel<<<128, 512, LSTM_SMEM>>>(whhf, whhb);                                          // launch 4 (ncu slot)

    addx_kernel<<<(BB*LL*HID + 255)/256, 256>>>();
    entity_att_kernel<<<BB, 128>>>(pos1, pos2);
    usq_kernel<<<(BB*NCAP + 255)/256, 256>>>();
    uhat_kernel<<<NCAP, 256>>>(wcaps);

    float *sptr, *vptr;
    cudaGetSymbolAddress((void**)&sptr, g_s);
    cudaGetSymbolAddress((void**)&vptr, g_v);
    cudaMemsetAsync(vptr, 0, BB*ODIM*sizeof(float));
    for (int it = 0; it < 3; ++it) {
        cudaMemsetAsync(sptr, 0, BB*ODIM*sizeof(float));
        route_kernel<<<BB*8, 320>>>(it == 0 ? 1 : 0, broute);
        squash_v_kernel<<<(BB*NCLS + 127)/128, 128>>>(out, it == 2 ? 1 : 0);
    }
    (void)in_sizes; (void)n_in; (void)out_size;
}

// round 4
// speedup vs baseline: 1.7540x; 1.7540x over previous
#include <cuda_runtime.h>
#include <math.h>
#include <stdint.h>

#define BB 128
#define LL 100
#define HID 256
#define IND 160
#define NCAP 1600
#define CAPD 16
#define NCLS 19
#define ODIM 304

// ---------------- device scratch ----------------
__device__ float g_xgf [BB*LL*1024];
__device__ float g_xgb [BB*LL*1024];
__device__ float g_hbuf[2*2*BB*HID];
__device__ float g_xf  [BB*LL*HID];
__device__ float g_xb  [BB*LL*HID];
__device__ float g_att [BB*LL];
__device__ float g_u   [BB*NCAP*CAPD];
__device__ float g_bb  [(size_t)BB*NCAP*NCLS];
__device__ float g_s   [BB*ODIM];
__device__ float g_v   [BB*ODIM];
__device__ unsigned long long g_bar = 0;

// ---------------- packed fp32x2 FMA ----------------
__device__ __forceinline__ float2 ffma2(float2 a, float2 b, float2 c) {
    float2 d;
    asm("fma.rn.f32x2 %0, %1, %2, %3;"
        : "=l"(reinterpret_cast<unsigned long long&>(d))
        : "l"(reinterpret_cast<unsigned long long&>(a)),
          "l"(reinterpret_cast<unsigned long long&>(b)),
          "l"(reinterpret_cast<unsigned long long&>(c)));
    return d;
}

// ---------------- grid barrier (monotone, graph-safe) ----------------
__device__ __forceinline__ void grid_barrier(unsigned nb) {
    __threadfence();
    __syncthreads();
    if (threadIdx.x == 0) {
        unsigned long long my = atomicAdd(&g_bar, 1ULL) + 1ULL;
        unsigned long long target = ((my + nb - 1ULL) / nb) * nb;
        while (*((volatile unsigned long long*)&g_bar) < target) { }
        __threadfence();
    }
    __syncthreads();
}

// ---------------- K1: xg GEMM with fused embedding gather ----------------
// C[M=12800, N=1024], K=160. A row m = b*100+l gathered from embedding tables.
__global__ void __launch_bounds__(256) gemm_xg_kernel(
        const int* __restrict__ word, const int* __restrict__ tag,
        const int* __restrict__ p1,   const int* __restrict__ p2,
        const float* __restrict__ we, const float* __restrict__ te,
        const float* __restrict__ p1e,const float* __restrict__ p2e,
        const float* __restrict__ wf, const float* __restrict__ wbk,
        const float* __restrict__ bif, const float* __restrict__ bhf,
        const float* __restrict__ bib, const float* __restrict__ bhb) {
    __shared__ float As[16][64];
    __shared__ float Ws[16][64];
    int dir = blockIdx.z;
    const float* W  = dir ? wbk : wf;
    const float* bi = dir ? bib : bif;
    const float* bh = dir ? bhb : bhf;
    float* C = dir ? g_xgb : g_xgf;
    int n0 = blockIdx.x * 64;
    int m0 = blockIdx.y * 64;
    int tid = threadIdx.x;
    int tx = tid & 15, ty = tid >> 4;
    int lrow = tid >> 2, lq = tid & 3;
    int bl = m0 + lrow;
    float acc[4][4] = {};
    for (int k0 = 0; k0 < 160; k0 += 16) {
        int d = k0 + lq * 4;
        const float* src;
        if (d < 100)      src = we + (size_t)word[bl]*100 + d;
        else if (d < 120) src = te  + tag[bl]*20 + (d-100);
        else if (d < 140) src = p1e + p1[bl]*20 + (d-120);
        else              src = p2e + p2[bl]*20 + (d-140);
        float4 av = *(const float4*)src;
        float4 wv = *(const float4*)(W + (size_t)(n0 + lrow) * 160 + k0 + lq * 4);
        As[lq*4+0][lrow] = av.x; As[lq*4+1][lrow] = av.y;
        As[lq*4+2][lrow] = av.z; As[lq*4+3][lrow] = av.w;
        Ws[lq*4+0][lrow] = wv.x; Ws[lq*4+1][lrow] = wv.y;
        Ws[lq*4+2][lrow] = wv.z; Ws[lq*4+3][lrow] = wv.w;
        __syncthreads();
        #pragma unroll
        for (int kk = 0; kk < 16; ++kk) {
            float a[4], w[4];
            #pragma unroll
            for (int e = 0; e < 4; ++e) { a[e] = As[kk][ty*4+e]; w[e] = Ws[kk][tx*4+e]; }
            #pragma unroll
            for (int i = 0; i < 4; ++i)
                #pragma unroll
                for (int j = 0; j < 4; ++j)
                    acc[i][j] += a[i] * w[j];
        }
        __syncthreads();
    }
    #pragma unroll
    for (int i = 0; i < 4; ++i) {
        int m = m0 + ty*4 + i;
        #pragma unroll
        for (int j = 0; j < 4; ++j) {
            int n = n0 + tx*4 + j;
            C[(size_t)m * 1024 + n] = acc[i][j] + bi[n] + bh[n];
        }
    }
}

// ---------------- K2: persistent BiLSTM (R1 form + xg prefetch) ----------------
#define WS_STRIDE 260
#define LSTM_SMEM ((4*16*WS_STRIDE + 16*256) * 4)

__global__ void __launch_bounds__(256, 2) lstm_kernel(
        const float* __restrict__ whh_f, const float* __restrict__ whh_b) {
    extern __shared__ float sm[];
    float* w_s = sm;                       // [4][16][WS_STRIDE]
    float* h_s = sm + 4*16*WS_STRIDE;      // [16][256]
    int blk = blockIdx.x;
    int dir = blk >> 7;
    int rem = blk & 127;
    int bt = rem >> 4;
    int ut = rem & 15;
    int b0 = bt * 16;
    int u0 = ut * 16;
    int tid = threadIdx.x;
    int b_local = tid >> 4;
    int u_local = tid & 15;
    int b = b0 + b_local;
    int u = u0 + u_local;
    const float* whh = dir ? whh_b : whh_f;
    const float* xg  = dir ? g_xgb : g_xgf;
    float* xout      = dir ? g_xb  : g_xf;

    for (int x = tid; x < 64*64; x += 256) {
        int row = x >> 6;
        int q   = x & 63;
        int g = row >> 4, ul = row & 15;
        int R = g*256 + u0 + ul;
        float4 v = *(const float4*)(whh + (size_t)R*256 + q*4);
        *(float4*)(w_s + (g*16+ul)*WS_STRIDE + q*4) = v;
    }
    float c_reg = 0.f;
    g_hbuf[((0*2 + dir)*BB + b)*HID + u] = 0.f;
    grid_barrier(gridDim.x);

    const float4* w0 = (const float4*)(w_s + (0*16 + u_local)*WS_STRIDE);
    const float4* w1 = (const float4*)(w_s + (1*16 + u_local)*WS_STRIDE);
    const float4* w2 = (const float4*)(w_s + (2*16 + u_local)*WS_STRIDE);
    const float4* w3 = (const float4*)(w_s + (3*16 + u_local)*WS_STRIDE);
    const float4* hv = (const float4*)(h_s + b_local*256);

    // prefetch xg for step 0
    int t0 = dir ? (LL-1) : 0;
    const float* xgp0 = xg + ((size_t)(b*LL + t0))*1024 + u;
    float xc0 = xgp0[0], xc1 = xgp0[256], xc2 = xgp0[512], xc3 = xgp0[768];

    int cur = 0;
    for (int step = 0; step < LL; ++step) {
        int t = dir ? (LL-1-step) : step;
        const float4* hsrc = (const float4*)(g_hbuf + ((size_t)(cur*2 + dir)*BB + b0)*HID);
        for (int q = tid; q < 16*64; q += 256) {
            float4 v = __ldcg(hsrc + q);
            *(float4*)(h_s + q*4) = v;
        }
        __syncthreads();

        float acc0 = xc0, acc1 = xc1, acc2 = xc2, acc3 = xc3;
        #pragma unroll 8
        for (int k = 0; k < 64; ++k) {
            float4 h4 = hv[k];
            float4 a;
            a = w0[k]; acc0 += h4.x*a.x + h4.y*a.y + h4.z*a.z + h4.w*a.w;
            a = w1[k]; acc1 += h4.x*a.x + h4.y*a.y + h4.z*a.z + h4.w*a.w;
            a = w2[k]; acc2 += h4.x*a.x + h4.y*a.y + h4.z*a.z + h4.w*a.w;
            a = w3[k]; acc3 += h4.x*a.x + h4.y*a.y + h4.z*a.z + h4.w*a.w;
        }
        float ig = 1.f / (1.f + expf(-acc0));
        float fg = 1.f / (1.f + expf(-acc1));
        float gt = tanhf(acc2);
        float og = 1.f / (1.f + expf(-acc3));
        c_reg = fg * c_reg + ig * gt;
        float h = og * tanhf(c_reg);
        g_hbuf[(((cur^1)*2 + dir)*BB + b)*HID + u] = h;
        xout[((size_t)(b*LL + t))*HID + u] = h;

        // prefetch next step's xg before the barrier spin
        if (step + 1 < LL) {
            int tn = dir ? (LL-2-step) : (step+1);
            const float* xgp = xg + ((size_t)(b*LL + tn))*1024 + u;
            xc0 = xgp[0]; xc1 = xgp[256]; xc2 = xgp[512]; xc3 = xgp[768];
        }
        grid_barrier(gridDim.x);
        cur ^= 1;
    }
}

// ---------------- K3: fused post (x=hf+hb, entity att, capsule squash) ----------------
__global__ void __launch_bounds__(256) post_kernel(const int* __restrict__ pos1,
                                                   const int* __restrict__ pos2) {
    int b = blockIdx.x;
    int tid = threadIdx.x;
    int w = tid >> 5, lane = tid & 31;
    __shared__ int e1s, e2s;
    __shared__ float he_s[256];
    __shared__ float lg[100];
    __shared__ float wred[8];
    __shared__ float mred, sred;
    if (tid < 100) {
        if (pos1[b*100 + tid] == 68) e1s = tid;
        if (pos2[b*100 + tid] == 68) e2s = tid;
    }
    // zero g_s for first routing pass
    g_s[b*304 + tid] = 0.f;
    if (tid < 48) g_s[b*304 + 256 + tid] = 0.f;
    __syncthreads();
    {
        size_t r1 = (size_t)(b*100 + e1s)*256 + tid;
        size_t r2 = (size_t)(b*100 + e2s)*256 + tid;
        he_s[tid] = g_xf[r1] + g_xb[r1] + g_xf[r2] + g_xb[r2];
    }
    __syncthreads();

    for (int l = 0; l < 100; ++l) {
        size_t off = (size_t)(b*100 + l)*256 + tid;
        float xv = g_xf[off] + g_xb[off];
        // capsule squash over 16-element groups (lanes of a group are contiguous)
        float sq = xv * xv;
        sq += __shfl_xor_sync(0xffffffffu, sq, 8);
        sq += __shfl_xor_sync(0xffffffffu, sq, 4);
        sq += __shfl_xor_sync(0xffffffffu, sq, 2);
        sq += __shfl_xor_sync(0xffffffffu, sq, 1);
        float sc = (sq / (1.f + sq)) * rsqrtf(sq + 1e-9f);
        g_u[(size_t)b*25600 + l*256 + tid] = xv * sc;
        // attention logit partial
        float pr = xv * he_s[tid];
        #pragma unroll
        for (int o2 = 16; o2; o2 >>= 1) pr += __shfl_xor_sync(0xffffffffu, pr, o2);
        if (lane == 0) wred[w] = pr;
        __syncthreads();
        if (tid == 0) {
            float s = 0.f;
            #pragma unroll
            for (int j = 0; j < 8; ++j) s += wred[j];
            lg[l] = s;
        }
        __syncthreads();
    }
    if (tid == 0) {
        float m = -1e30f;
        for (int l = 0; l < 100; ++l) m = fmaxf(m, lg[l]);
        float ssum = 0.f;
        for (int l = 0; l < 100; ++l) ssum += expf(lg[l] - m);
        mred = m; sred = ssum;
    }
    __syncthreads();
    if (tid < 100) g_att[b*100 + tid] = expf(lg[tid] - mred) / sred;
}

// ---------------- K4: fused routing pass (recompute u_hat from W_caps) ----------------
// grid: 32 i-chunks (50 i each) x 8 b-chunks (16 b each) = 256 blocks, 512 threads.
// warp <-> one b; lane owns od pairs od = 64k + 2*lane (k<5, od<304).
// W tile [16][304] double-buffered in smem; s accumulated in registers.
#define R_W2PAD 2448                       // float2 per W buffer (2432 + OOB pad)
#define R_WOFF0 0
#define R_WOFF1 (2*R_W2PAD)                // in floats
#define R_VOFF  (4*R_W2PAD)
#define R_CWOFF (R_VOFF + 4864)
#define R_SMEM  ((R_CWOFF + 320) * 4)

__global__ void __launch_bounds__(512) route_kernel(int first,
        const float* __restrict__ broute, const float* __restrict__ Wc) {
    extern __shared__ float rsm[];
    float* Wb0 = rsm + R_WOFF0;
    float* Wb1 = rsm + R_WOFF1;
    float* v_s = rsm + R_VOFF;     // [16][304]
    float* cw  = rsm + R_CWOFF;    // [16][20]

    int ichunk = blockIdx.x >> 3;
    int bch    = blockIdx.x & 7;
    int i0 = ichunk * 50;
    int b0 = bch * 16;
    int tid = threadIdx.x;
    int w = tid >> 5, lane = tid & 31;
    int b = b0 + w;

    if (!first) {
        for (int j = tid; j < 4864; j += 512) {
            int br = j / 304, od = j - br*304;
            v_s[j] = g_v[(b0 + br)*304 + od];
        }
    }
    // load W tile for i0
    {
        const float4* src = (const float4*)(Wc + (size_t)i0 * 4864);
        #pragma unroll
        for (int t = 0; t < 3; ++t) {
            int j = tid + t*512;
            if (j < 1216) ((float4*)Wb0)[j] = src[j];
        }
    }
    float2 sa[5];
    #pragma unroll
    for (int k = 0; k < 5; ++k) sa[k] = make_float2(0.f, 0.f);
    __syncthreads();

    for (int ii = 0; ii < 50; ++ii) {
        int i = i0 + ii;
        float* curW = (ii & 1) ? Wb1 : Wb0;
        float* nxtW = (ii & 1) ? Wb0 : Wb1;
        // issue prefetch loads for next i
        float4 pf0, pf1, pf2;
        if (ii < 49) {
            const float4* src = (const float4*)(Wc + (size_t)(i+1) * 4864);
            int j0 = tid, j1 = tid + 512, j2 = tid + 1024;
            pf0 = src[j0];
            pf1 = src[j1];
            if (j2 < 1216) pf2 = src[j2];
        }

        float uu = (lane < 16) ? g_u[(size_t)b*25600 + i*16 + lane] : 0.f;
        float av_ = (lane == 0) ? g_att[b*LL + (i >> 4)] : 0.f;
        float attv = __shfl_sync(0xffffffffu, av_, 0);

        // u_hat (f32x2): uh[k] covers od = 64k + 2*lane
        float2 uh[5];
        #pragma unroll
        for (int k = 0; k < 5; ++k) uh[k] = make_float2(0.f, 0.f);
        const float2* W2 = (const float2*)curW;
        #pragma unroll
        for (int c = 0; c < 16; ++c) {
            float uc = __shfl_sync(0xffffffffu, uu, c);
            float2 uc2 = make_float2(uc, uc);
            const float2* Wr = W2 + c*152 + lane;
            #pragma unroll
            for (int k = 0; k < 5; ++k)
                uh[k] = ffma2(uc2, Wr[k*32], uh[k]);
        }

        // agreement dot with v (skip on first pass)
        if (!first) {
            const float2* v2 = (const float2*)v_s + w*152 + lane;
            #pragma unroll
            for (int k = 0; k < 5; ++k) {
                float pk = 0.f;
                if (k < 4 || lane < 24) {
                    float2 vv = v2[k*32];
                    pk = uh[k].x*vv.x + uh[k].y*vv.y;
                }
                pk += __shfl_xor_sync(0xffffffffu, pk, 4);
                pk += __shfl_xor_sync(0xffffffffu, pk, 2);
                pk += __shfl_xor_sync(0xffffffffu, pk, 1);
                if ((lane & 7) == 0) cw[w*20 + 4*k + (lane >> 3)] = pk;
            }
        }
        __syncwarp();

        // bb update + softmax over 19 classes (lane = o)
        float bbv = 0.f;
        if (lane < 19) {
            size_t bbi = ((size_t)b*NCAP + i)*NCLS + lane;
            bbv = first ? broute[i*NCLS + lane] : (g_bb[bbi] + cw[w*20 + lane]);
            g_bb[bbi] = bbv;
        }
        float val = (lane < 19) ? bbv : -1e30f;
        float m = val;
        #pragma unroll
        for (int o2 = 16; o2; o2 >>= 1) m = fmaxf(m, __shfl_xor_sync(0xffffffffu, m, o2));
        float e = (lane < 19) ? expf(val - m) : 0.f;
        float ssum = e;
        #pragma unroll
        for (int o2 = 16; o2; o2 >>= 1) ssum += __shfl_xor_sync(0xffffffffu, ssum, o2);
        if (lane < 19) cw[w*20 + lane] = (e / ssum) * attv;
        __syncwarp();

        // accumulate s partials in registers
        #pragma unroll
        for (int k = 0; k < 5; ++k) {
            if (k < 4 || lane < 24) {
                float cc = cw[w*20 + ((k*64 + 2*lane) >> 4)];
                sa[k].x += cc * uh[k].x;
                sa[k].y += cc * uh[k].y;
            }
        }

        // complete prefetch stores
        if (ii < 49) {
            int j0 = tid, j1 = tid + 512, j2 = tid + 1024;
            ((float4*)nxtW)[j0] = pf0;
            ((float4*)nxtW)[j1] = pf1;
            if (j2 < 1216) ((float4*)nxtW)[j2] = pf2;
        }
        __syncthreads();
    }

    #pragma unroll
    for (int k = 0; k < 5; ++k) {
        if (k < 4 || lane < 24) {
            int od = k*64 + 2*lane;
            atomicAdd(&g_s[b*ODIM + od],     sa[k].x);
            atomicAdd(&g_s[b*ODIM + od + 1], sa[k].y);
        }
    }
}

// ---------------- K5: v = squash(s), zero g_s for next pass, final lengths ----------------
__global__ void squash_v_kernel(float* __restrict__ out, int last) {
    int idx = blockIdx.x * blockDim.x + threadIdx.x;
    if (idx >= BB*NCLS) return;
    float* sp = g_s + (size_t)idx * 16;
    float4 a0 = *(const float4*)(sp + 0);
    float4 a1 = *(const float4*)(sp + 4);
    float4 a2 = *(const float4*)(sp + 8);
    float4 a3 = *(const float4*)(sp + 12);
    float n2 = a0.x*a0.x + a0.y*a0.y + a0.z*a0.z + a0.w*a0.w
             + a1.x*a1.x + a1.y*a1.y + a1.z*a1.z + a1.w*a1.w
             + a2.x*a2.x + a2.y*a2.y + a2.z*a2.z + a2.w*a2.w
             + a3.x*a3.x + a3.y*a3.y + a3.z*a3.z + a3.w*a3.w;
    float sc = (n2 / (1.f + n2)) * rsqrtf(n2 + 1e-9f);
    float* vp = g_v + (size_t)idx * 16;
    a0.x*=sc; a0.y*=sc; a0.z*=sc; a0.w*=sc;
    a1.x*=sc; a1.y*=sc; a1.z*=sc; a1.w*=sc;
    a2.x*=sc; a2.y*=sc; a2.z*=sc; a2.w*=sc;
    a3.x*=sc; a3.y*=sc; a3.z*=sc; a3.w*=sc;
    *(float4*)(vp + 0)  = a0; *(float4*)(vp + 4)  = a1;
    *(float4*)(vp + 8)  = a2; *(float4*)(vp + 12) = a3;
    // zero s for next pass's atomics
    float4 z = make_float4(0.f, 0.f, 0.f, 0.f);
    *(float4*)(sp + 0) = z; *(float4*)(sp + 4)  = z;
    *(float4*)(sp + 8) = z; *(float4*)(sp + 12) = z;
    if (last) out[idx] = sqrtf(n2 * sc * sc + 1e-9f);
}

// ---------------- launch ----------------
extern "C" void kernel_launch(void* const* d_in, const int* in_sizes, int n_in,
                              void* d_out, int out_size) {
    const int*   word   = (const int*)d_in[0];
    const int*   tag    = (const int*)d_in[1];
    const int*   pos1   = (const int*)d_in[2];
    const int*   pos2   = (const int*)d_in[3];
    const float* we     = (const float*)d_in[4];
    const float* te     = (const float*)d_in[5];
    const float* p1e    = (const float*)d_in[6];
    const float* p2e    = (const float*)d_in[7];
    const float* wihf   = (const float*)d_in[8];
    const float* whhf   = (const float*)d_in[9];
    const float* bihf   = (const float*)d_in[10];
    const float* bhhf   = (const float*)d_in[11];
    const float* wihb   = (const float*)d_in[12];
    const float* whhb   = (const float*)d_in[13];
    const float* bihb   = (const float*)d_in[14];
    const float* bhhb   = (const float*)d_in[15];
    const float* wcaps  = (const float*)d_in[16];
    const float* broute = (const float*)d_in[17];
    float* out = (float*)d_out;

    cudaFuncSetAttribute(lstm_kernel,  cudaFuncAttributeMaxDynamicSharedMemorySize, LSTM_SMEM);
    cudaFuncSetAttribute(route_kernel, cudaFuncAttributeMaxDynamicSharedMemorySize, R_SMEM);

    dim3 gg(16, 200, 2);
    gemm_xg_kernel<<<gg, 256>>>(word, tag, pos1, pos2, we, te, p1e, p2e,
                                wihf, wihb, bihf, bhhf, bihb, bhhb);     // launch 1

    lstm_kernel<<<256, 256, LSTM_SMEM>>>(whhf, whhb);                    // launch 2

    post_kernel<<<BB, 256>>>(pos1, pos2);                                // launch 3

    for (int it = 0; it < 3; ++it) {
        route_kernel<<<256, 512, R_SMEM>>>(it == 0 ? 1 : 0, broute, wcaps); // launch 4 = ncu slot (pass 1)
        squash_v_kernel<<<(BB*NCLS + 127)/128, 128>>>(out, it == 2 ? 1 : 0);
    }
    (void)in_sizes; (void)n_in; (void)out_size;
}

// round 5
// speedup vs baseline: 1.7898x; 1.0204x over previous
#include <cuda_runtime.h>
#include <math.h>
#include <stdint.h>

#define BB 128
#define LL 100
#define HID 256
#define NCAP 1600
#define NCLS 19
#define ODIM 304

// ---------------- device scratch ----------------
__device__ float g_xgf [BB*LL*1024];
__device__ float g_xgb [BB*LL*1024];
__device__ float g_hbuf[2*2*BB*HID];
__device__ float g_xf  [BB*LL*HID];
__device__ float g_xb  [BB*LL*HID];
__device__ float g_att [BB*LL];
__device__ float g_u   [BB*NCAP*16];
__device__ float g_bb  [(size_t)BB*NCAP*NCLS];
__device__ float g_s   [BB*ODIM];
__device__ float g_v   [BB*ODIM];
__device__ unsigned long long g_bar = 0;

// ---------------- packed fp32x2 FMA ----------------
__device__ __forceinline__ float2 ffma2(float2 a, float2 b, float2 c) {
    float2 d;
    asm("fma.rn.f32x2 %0, %1, %2, %3;"
        : "=l"(reinterpret_cast<unsigned long long&>(d))
        : "l"(reinterpret_cast<unsigned long long&>(a)),
          "l"(reinterpret_cast<unsigned long long&>(b)),
          "l"(reinterpret_cast<unsigned long long&>(c)));
    return d;
}

// ---------------- grid barrier (monotone, graph-safe) ----------------
__device__ __forceinline__ void grid_barrier(unsigned nb) {
    __threadfence();
    __syncthreads();
    if (threadIdx.x == 0) {
        unsigned long long my = atomicAdd(&g_bar, 1ULL) + 1ULL;
        unsigned long long target = ((my + nb - 1ULL) / nb) * nb;
        while (*((volatile unsigned long long*)&g_bar) < target) { }
        __threadfence();
    }
    __syncthreads();
}

// ---------------- K1: xg GEMM with fused embedding gather ----------------
__global__ void __launch_bounds__(256) gemm_xg_kernel(
        const int* __restrict__ word, const int* __restrict__ tag,
        const int* __restrict__ p1,   const int* __restrict__ p2,
        const float* __restrict__ we, const float* __restrict__ te,
        const float* __restrict__ p1e,const float* __restrict__ p2e,
        const float* __restrict__ wf, const float* __restrict__ wbk,
        const float* __restrict__ bif, const float* __restrict__ bhf,
        const float* __restrict__ bib, const float* __restrict__ bhb) {
    __shared__ float As[16][64];
    __shared__ float Ws[16][64];
    int dir = blockIdx.z;
    const float* W  = dir ? wbk : wf;
    const float* bi = dir ? bib : bif;
    const float* bh = dir ? bhb : bhf;
    float* C = dir ? g_xgb : g_xgf;
    int n0 = blockIdx.x * 64;
    int m0 = blockIdx.y * 64;
    int tid = threadIdx.x;
    int tx = tid & 15, ty = tid >> 4;
    int lrow = tid >> 2, lq = tid & 3;
    int bl = m0 + lrow;
    float acc[4][4] = {};
    for (int k0 = 0; k0 < 160; k0 += 16) {
        int d = k0 + lq * 4;
        const float* src;
        if (d < 100)      src = we + (size_t)word[bl]*100 + d;
        else if (d < 120) src = te  + tag[bl]*20 + (d-100);
        else if (d < 140) src = p1e + p1[bl]*20 + (d-120);
        else              src = p2e + p2[bl]*20 + (d-140);
        float4 av = *(const float4*)src;
        float4 wv = *(const float4*)(W + (size_t)(n0 + lrow) * 160 + k0 + lq * 4);
        As[lq*4+0][lrow] = av.x; As[lq*4+1][lrow] = av.y;
        As[lq*4+2][lrow] = av.z; As[lq*4+3][lrow] = av.w;
        Ws[lq*4+0][lrow] = wv.x; Ws[lq*4+1][lrow] = wv.y;
        Ws[lq*4+2][lrow] = wv.z; Ws[lq*4+3][lrow] = wv.w;
        __syncthreads();
        #pragma unroll
        for (int kk = 0; kk < 16; ++kk) {
            float a[4], w[4];
            #pragma unroll
            for (int e = 0; e < 4; ++e) { a[e] = As[kk][ty*4+e]; w[e] = Ws[kk][tx*4+e]; }
            #pragma unroll
            for (int i = 0; i < 4; ++i)
                #pragma unroll
                for (int j = 0; j < 4; ++j)
                    acc[i][j] += a[i] * w[j];
        }
        __syncthreads();
    }
    #pragma unroll
    for (int i = 0; i < 4; ++i) {
        int m = m0 + ty*4 + i;
        #pragma unroll
        for (int j = 0; j < 4; ++j) {
            int n = n0 + tx*4 + j;
            C[(size_t)m * 1024 + n] = acc[i][j] + bi[n] + bh[n];
        }
    }
}

// ---------------- K2: persistent BiLSTM, conflict-free smem layout ----------------
// 256 blocks = 2 dir x 8 btile x 16 utile. Warp = 4b x 8u.
// w_t: [4g][64 k4][u pad 17] float4 ; h_s: [16b][k4 pad 69] float4.
#define WT_F4 (4*64*17)
#define HS_F4 (16*69)
#define LSTM_SMEM ((WT_F4 + HS_F4) * 16)

__global__ void __launch_bounds__(256, 2) lstm_kernel(
        const float* __restrict__ whh_f, const float* __restrict__ whh_b) {
    extern __shared__ float4 sm4[];
    float4* w_t = sm4;             // idx (g*64+k4)*17 + u
    float4* h_s = sm4 + WT_F4;     // idx b*69 + k4
    int blk = blockIdx.x;
    int dir = blk >> 7;
    int rem = blk & 127;
    int bt = rem >> 4;
    int ut = rem & 15;
    int b0 = bt * 16;
    int u0 = ut * 16;
    int tid = threadIdx.x;
    int ww = tid >> 5, lane = tid & 31;
    int b_local = (ww >> 1) * 4 + (lane >> 3);
    int u_local = (ww & 1) * 8 + (lane & 7);
    int b = b0 + b_local;
    int u = u0 + u_local;
    const float* whh = dir ? whh_b : whh_f;
    const float* xg  = dir ? g_xgb : g_xgf;
    float* xout      = dir ? g_xb  : g_xf;

    // load w_hh slice transposed: w_t[g][k4][u] = whh[g*256+u0+u][k4*4..+4]
    for (int x = tid; x < 4*64*16; x += 256) {
        int uu = x & 15;
        int k4 = (x >> 4) & 63;
        int g  = x >> 10;
        int R  = g*256 + u0 + uu;
        float4 v = *(const float4*)(whh + (size_t)R*256 + k4*4);
        w_t[(g*64 + k4)*17 + uu] = v;
    }
    float c_reg = 0.f;
    g_hbuf[((0*2 + dir)*BB + b)*HID + u] = 0.f;
    grid_barrier(gridDim.x);

    const float4* hrow = h_s + b_local*69;
    const float4* wp = w_t + u_local;

    // prefetch xg for step 0
    int t0 = dir ? (LL-1) : 0;
    const float* xgp0 = xg + ((size_t)(b*LL + t0))*1024 + u;
    float xc0 = xgp0[0], xc1 = xgp0[256], xc2 = xgp0[512], xc3 = xgp0[768];

    int cur = 0;
    for (int step = 0; step < LL; ++step) {
        int t = dir ? (LL-1-step) : step;
        const float4* hsrc = (const float4*)(g_hbuf + ((size_t)(cur*2 + dir)*BB + b0)*HID);
        for (int x = tid; x < 16*64; x += 256) {
            float4 v = __ldcg(hsrc + x);
            h_s[(x >> 6)*69 + (x & 63)] = v;
        }
        __syncthreads();

        float2 a0 = make_float2(0.f,0.f), a1 = make_float2(0.f,0.f);
        float2 a2 = make_float2(0.f,0.f), a3 = make_float2(0.f,0.f);
        #pragma unroll 8
        for (int k4 = 0; k4 < 64; ++k4) {
            float4 h4 = hrow[k4];
            float2 hA = make_float2(h4.x, h4.y);
            float2 hB = make_float2(h4.z, h4.w);
            float4 w;
            w = wp[(0*64 + k4)*17]; a0 = ffma2(hA, make_float2(w.x,w.y), a0); a0 = ffma2(hB, make_float2(w.z,w.w), a0);
            w = wp[(1*64 + k4)*17]; a1 = ffma2(hA, make_float2(w.x,w.y), a1); a1 = ffma2(hB, make_float2(w.z,w.w), a1);
            w = wp[(2*64 + k4)*17]; a2 = ffma2(hA, make_float2(w.x,w.y), a2); a2 = ffma2(hB, make_float2(w.z,w.w), a2);
            w = wp[(3*64 + k4)*17]; a3 = ffma2(hA, make_float2(w.x,w.y), a3); a3 = ffma2(hB, make_float2(w.z,w.w), a3);
        }
        float gi = xc0 + a0.x + a0.y;
        float gf = xc1 + a1.x + a1.y;
        float gg = xc2 + a2.x + a2.y;
        float go = xc3 + a3.x + a3.y;
        float ig = 1.f / (1.f + expf(-gi));
        float fg = 1.f / (1.f + expf(-gf));
        float gt = tanhf(gg);
        float og = 1.f / (1.f + expf(-go));
        c_reg = fg * c_reg + ig * gt;
        float h = og * tanhf(c_reg);
        g_hbuf[(((cur^1)*2 + dir)*BB + b)*HID + u] = h;
        xout[((size_t)(b*LL + t))*HID + u] = h;

        if (step + 1 < LL) {
            int tn = dir ? (LL-2-step) : (step+1);
            const float* xgp = xg + ((size_t)(b*LL + tn))*1024 + u;
            xc0 = xgp[0]; xc1 = xgp[256]; xc2 = xgp[512]; xc3 = xgp[768];
        }
        grid_barrier(gridDim.x);
        cur ^= 1;
    }
}

// ---------------- K3: fused post (x=hf+hb, entity att, capsule squash) ----------------
__global__ void __launch_bounds__(256) post_kernel(const int* __restrict__ pos1,
                                                   const int* __restrict__ pos2) {
    int b = blockIdx.x;
    int tid = threadIdx.x;
    int w = tid >> 5, lane = tid & 31;
    __shared__ int e1s, e2s;
    __shared__ float he_s[256];
    __shared__ float lg[100];
    __shared__ float wred[8];
    __shared__ float mred, sred;
    if (tid < 100) {
        if (pos1[b*100 + tid] == 68) e1s = tid;
        if (pos2[b*100 + tid] == 68) e2s = tid;
    }
    g_s[b*304 + tid] = 0.f;
    if (tid < 48) g_s[b*304 + 256 + tid] = 0.f;
    __syncthreads();
    {
        size_t r1 = (size_t)(b*100 + e1s)*256 + tid;
        size_t r2 = (size_t)(b*100 + e2s)*256 + tid;
        he_s[tid] = g_xf[r1] + g_xb[r1] + g_xf[r2] + g_xb[r2];
    }
    __syncthreads();

    for (int l = 0; l < 100; ++l) {
        size_t off = (size_t)(b*100 + l)*256 + tid;
        float xv = g_xf[off] + g_xb[off];
        float sq = xv * xv;
        sq += __shfl_xor_sync(0xffffffffu, sq, 8);
        sq += __shfl_xor_sync(0xffffffffu, sq, 4);
        sq += __shfl_xor_sync(0xffffffffu, sq, 2);
        sq += __shfl_xor_sync(0xffffffffu, sq, 1);
        float sc = (sq / (1.f + sq)) * rsqrtf(sq + 1e-9f);
        g_u[(size_t)b*25600 + l*256 + tid] = xv * sc;
        float pr = xv * he_s[tid];
        #pragma unroll
        for (int o2 = 16; o2; o2 >>= 1) pr += __shfl_xor_sync(0xffffffffu, pr, o2);
        if (lane == 0) wred[w] = pr;
        __syncthreads();
        if (tid == 0) {
            float s = 0.f;
            #pragma unroll
            for (int j = 0; j < 8; ++j) s += wred[j];
            lg[l] = s;
        }
        __syncthreads();
    }
    if (tid == 0) {
        float m = -1e30f;
        for (int l = 0; l < 100; ++l) m = fmaxf(m, lg[l]);
        float ssum = 0.f;
        for (int l = 0; l < 100; ++l) ssum += expf(lg[l] - m);
        mred = m; sred = ssum;
    }
    __syncthreads();
    if (tid < 100) g_att[b*100 + tid] = expf(lg[tid] - mred) / sred;
}

// ---------------- K4: routing pass, 8b-per-thread, shfl u-broadcast ----------------
// grid: 32 i-chunks x 8 b-chunks = 256 blocks, 320 threads.
// thread: half = tid/160 (8 b's), op = tid%160 (od-pair, <152 active).
__global__ void __launch_bounds__(320) route_kernel(int first, int last,
        const float* __restrict__ broute, const float* __restrict__ Wc) {
    __shared__ float2 Wb[2][16*152];
    __shared__ float bbsm[16][20];
    __shared__ float csm[16][20];

    int ichunk = blockIdx.x >> 3;
    int bch    = blockIdx.x & 7;
    int i0 = ichunk * 50;
    int tid = threadIdx.x;
    int lane = tid & 31;
    int warp = tid >> 5;
    int half = tid / 160;
    int op   = tid % 160;
    bool act = op < 152;
    int opc  = act ? op : 0;
    int o    = opc >> 3;
    int bbase = bch*16 + half*8;

    // v held in registers across the whole i-loop
    float2 vv[8];
    #pragma unroll
    for (int j = 0; j < 8; ++j) vv[j] = make_float2(0.f, 0.f);
    if (!first && act) {
        #pragma unroll
        for (int j = 0; j < 8; ++j)
            vv[j] = *(const float2*)&g_v[(bbase + j)*ODIM + 2*op];
    }

    // stage W[i0] into buffer 0
    {
        const float4* src = (const float4*)(Wc + (size_t)i0 * 4864);
        float4* dst = (float4*)&Wb[0][0];
        for (int x = tid; x < 1216; x += 320) dst[x] = src[x];
    }
    float2 sa[8];
    #pragma unroll
    for (int j = 0; j < 8; ++j) sa[j] = make_float2(0.f, 0.f);
    __syncthreads();

    for (int ii = 0; ii < 50; ++ii) {
        int i = i0 + ii;
        const float2* Wcur = &Wb[ii & 1][0];
        float4* Wnxt = (float4*)&Wb[(ii & 1) ^ 1][0];

        // register-prefetch next W tile
        float4 pf0, pf1, pf2, pf3;
        if (ii < 49) {
            const float4* src = (const float4*)(Wc + (size_t)(i+1) * 4864);
            pf0 = src[tid];
            pf1 = src[tid + 320];
            pf2 = src[tid + 640];
            if (tid + 960 < 1216) pf3 = src[tid + 960];
        }

        // preload u[8b][16c] into 4 regs (value idx = j*16+c, lane holds idx%32, reg idx/32)
        float ureg[4];
        #pragma unroll
        for (int r = 0; r < 4; ++r) {
            int idx = r*32 + lane;
            int j = idx >> 4, c = idx & 15;
            ureg[r] = g_u[(size_t)(bbase + j)*25600 + i*16 + c];
        }

        // u_hat: uh[j] = sum_c u[j][c] * W[c][od-pair]
        float2 uh[8];
        #pragma unroll
        for (int j = 0; j < 8; ++j) uh[j] = make_float2(0.f, 0.f);
        #pragma unroll
        for (int c = 0; c < 16; ++c) {
            float2 wv = Wcur[c*152 + opc];
            #pragma unroll
            for (int j = 0; j < 8; ++j) {
                const int idx = j*16 + c;
                float uv = __shfl_sync(0xffffffffu, ureg[idx >> 5], idx & 31);
                uh[j] = ffma2(make_float2(uv, uv), wv, uh[j]);
            }
        }

        // agreement dot with v -> bbsm (skip pass 1)
        if (!first) {
            #pragma unroll
            for (int j = 0; j < 8; ++j) {
                float p = uh[j].x*vv[j].x + uh[j].y*vv[j].y;
                p += __shfl_xor_sync(0xffffffffu, p, 1);
                p += __shfl_xor_sync(0xffffffffu, p, 2);
                p += __shfl_xor_sync(0xffffffffu, p, 4);
                if (act && (opc & 7) == 0) bbsm[half*8 + j][o] = p;
            }
        }
        __syncthreads();

        // softmax per b (warps 0-7, two b each)
        if (warp < 8) {
            #pragma unroll
            for (int rep = 0; rep < 2; ++rep) {
                int bsel = warp + rep*8;
                int bglob = bch*16 + bsel;
                float bbv = 0.f;
                if (lane < 19) {
                    if (first) {
                        bbv = broute[i*NCLS + lane];
                    } else {
                        bbv = g_bb[((size_t)bglob*NCAP + i)*NCLS + lane] + bbsm[bsel][lane];
                    }
                    if (!last) g_bb[((size_t)bglob*NCAP + i)*NCLS + lane] = bbv;
                }
                float val = (lane < 19) ? bbv : -1e30f;
                float m = val;
                #pragma unroll
                for (int o2 = 16; o2; o2 >>= 1) m = fmaxf(m, __shfl_xor_sync(0xffffffffu, m, o2));
                float e = (lane < 19) ? expf(val - m) : 0.f;
                float ssum = e;
                #pragma unroll
                for (int o2 = 16; o2; o2 >>= 1) ssum += __shfl_xor_sync(0xffffffffu, ssum, o2);
                float attv = g_att[bglob*LL + (i >> 4)];
                if (lane < 19) csm[bsel][lane] = (e / ssum) * attv;
            }
        }
        __syncthreads();

        // s accumulate in registers
        if (act) {
            #pragma unroll
            for (int j = 0; j < 8; ++j) {
                float cc = csm[half*8 + j][o];
                sa[j] = ffma2(make_float2(cc, cc), uh[j], sa[j]);
            }
        }

        // complete W prefetch stores (visible to all after next iter's first sync)
        if (ii < 49) {
            Wnxt[tid]       = pf0;
            Wnxt[tid + 320] = pf1;
            Wnxt[tid + 640] = pf2;
            if (tid + 960 < 1216) Wnxt[tid + 960] = pf3;
        }
        __syncthreads();
    }

    if (act) {
        #pragma unroll
        for (int j = 0; j < 8; ++j) {
            atomicAdd(&g_s[(bbase + j)*ODIM + 2*op],     sa[j].x);
            atomicAdd(&g_s[(bbase + j)*ODIM + 2*op + 1], sa[j].y);
        }
    }
}

// ---------------- K5: v = squash(s), zero g_s, final lengths ----------------
__global__ void squash_v_kernel(float* __restrict__ out, int last) {
    int idx = blockIdx.x * blockDim.x + threadIdx.x;
    if (idx >= BB*NCLS) return;
    float* sp = g_s + (size_t)idx * 16;
    float4 a0 = *(const float4*)(sp + 0);
    float4 a1 = *(const float4*)(sp + 4);
    float4 a2 = *(const float4*)(sp + 8);
    float4 a3 = *(const float4*)(sp + 12);
    float n2 = a0.x*a0.x + a0.y*a0.y + a0.z*a0.z + a0.w*a0.w
             + a1.x*a1.x + a1.y*a1.y + a1.z*a1.z + a1.w*a1.w
             + a2.x*a2.x + a2.y*a2.y + a2.z*a2.z + a2.w*a2.w
             + a3.x*a3.x + a3.y*a3.y + a3.z*a3.z + a3.w*a3.w;
    float sc = (n2 / (1.f + n2)) * rsqrtf(n2 + 1e-9f);
    float* vp = g_v + (size_t)idx * 16;
    a0.x*=sc; a0.y*=sc; a0.z*=sc; a0.w*=sc;
    a1.x*=sc; a1.y*=sc; a1.z*=sc; a1.w*=sc;
    a2.x*=sc; a2.y*=sc; a2.z*=sc; a2.w*=sc;
    a3.x*=sc; a3.y*=sc; a3.z*=sc; a3.w*=sc;
    *(float4*)(vp + 0)  = a0; *(float4*)(vp + 4)  = a1;
    *(float4*)(vp + 8)  = a2; *(float4*)(vp + 12) = a3;
    float4 z = make_float4(0.f, 0.f, 0.f, 0.f);
    *(float4*)(sp + 0) = z; *(float4*)(sp + 4)  = z;
    *(float4*)(sp + 8) = z; *(float4*)(sp + 12) = z;
    if (last) out[idx] = sqrtf(n2 * sc * sc + 1e-9f);
}

// ---------------- launch ----------------
extern "C" void kernel_launch(void* const* d_in, const int* in_sizes, int n_in,
                              void* d_out, int out_size) {
    const int*   word   = (const int*)d_in[0];
    const int*   tag    = (const int*)d_in[1];
    const int*   pos1   = (const int*)d_in[2];
    const int*   pos2   = (const int*)d_in[3];
    const float* we     = (const float*)d_in[4];
    const float* te     = (const float*)d_in[5];
    const float* p1e    = (const float*)d_in[6];
    const float* p2e    = (const float*)d_in[7];
    const float* wihf   = (const float*)d_in[8];
    const float* whhf   = (const float*)d_in[9];
    const float* bihf   = (const float*)d_in[10];
    const float* bhhf   = (const float*)d_in[11];
    const float* wihb   = (const float*)d_in[12];
    const float* whhb   = (const float*)d_in[13];
    const float* bihb   = (const float*)d_in[14];
    const float* bhhb   = (const float*)d_in[15];
    const float* wcaps  = (const float*)d_in[16];
    const float* broute = (const float*)d_in[17];
    float* out = (float*)d_out;

    cudaFuncSetAttribute(lstm_kernel, cudaFuncAttributeMaxDynamicSharedMemorySize, LSTM_SMEM);

    dim3 gg(16, 200, 2);
    gemm_xg_kernel<<<gg, 256>>>(word, tag, pos1, pos2, we, te, p1e, p2e,
                                wihf, wihb, bihf, bhhf, bihb, bhhb);     // launch 1

    lstm_kernel<<<256, 256, LSTM_SMEM>>>(whhf, whhb);                    // launch 2

    post_kernel<<<BB, 256>>>(pos1, pos2);                                // launch 3

    for (int it = 0; it < 3; ++it) {
        route_kernel<<<256, 320>>>(it == 0 ? 1 : 0, it == 2 ? 1 : 0, broute, wcaps); // launch 4 = ncu slot
        squash_v_kernel<<<(BB*NCLS + 127)/128, 128>>>(out, it == 2 ? 1 : 0);
    }
    (void)in_sizes; (void)n_in; (void)out_size;
}

// round 6
// speedup vs baseline: 1.9167x; 1.0709x over previous
#include <cuda_runtime.h>
#include <math.h>
#include <stdint.h>

#define BB 128
#define LL 100
#define HID 256
#define NCAP 1600
#define NCLS 19
#define ODIM 304

// ---------------- device scratch ----------------
__device__ float g_xgf [BB*LL*1024];
__device__ float g_xgb [BB*LL*1024];
__device__ float g_hbuf[4*2*BB*HID];          // quad-buffered h state
__device__ float g_xf  [BB*LL*HID];
__device__ float g_xb  [BB*LL*HID];
__device__ float g_att [BB*LL];
__device__ float g_u   [BB*NCAP*16];
__device__ float g_bb  [(size_t)BB*NCAP*NCLS];
__device__ float g_s   [BB*ODIM];
__device__ float g_v   [BB*ODIM];
__device__ __align__(64) int g_hflags[16][16]; // [dir*8+bt][ut]

// ---------------- packed fp32x2 FMA ----------------
__device__ __forceinline__ float2 ffma2(float2 a, float2 b, float2 c) {
    float2 d;
    asm("fma.rn.f32x2 %0, %1, %2, %3;"
        : "=l"(reinterpret_cast<unsigned long long&>(d))
        : "l"(reinterpret_cast<unsigned long long&>(a)),
          "l"(reinterpret_cast<unsigned long long&>(b)),
          "l"(reinterpret_cast<unsigned long long&>(c)));
    return d;
}

// ---------------- K1: xg GEMM with fused embedding gather ----------------
__global__ void __launch_bounds__(256) gemm_xg_kernel(
        const int* __restrict__ word, const int* __restrict__ tag,
        const int* __restrict__ p1,   const int* __restrict__ p2,
        const float* __restrict__ we, const float* __restrict__ te,
        const float* __restrict__ p1e,const float* __restrict__ p2e,
        const float* __restrict__ wf, const float* __restrict__ wbk,
        const float* __restrict__ bif, const float* __restrict__ bhf,
        const float* __restrict__ bib, const float* __restrict__ bhb) {
    __shared__ float As[16][64];
    __shared__ float Ws[16][64];
    int dir = blockIdx.z;
    const float* W  = dir ? wbk : wf;
    const float* bi = dir ? bib : bif;
    const float* bh = dir ? bhb : bhf;
    float* C = dir ? g_xgb : g_xgf;
    int n0 = blockIdx.x * 64;
    int m0 = blockIdx.y * 64;
    int tid = threadIdx.x;
    int tx = tid & 15, ty = tid >> 4;
    int lrow = tid >> 2, lq = tid & 3;
    int bl = m0 + lrow;
    float acc[4][4] = {};
    for (int k0 = 0; k0 < 160; k0 += 16) {
        int d = k0 + lq * 4;
        const float* src;
        if (d < 100)      src = we + (size_t)word[bl]*100 + d;
        else if (d < 120) src = te  + tag[bl]*20 + (d-100);
        else if (d < 140) src = p1e + p1[bl]*20 + (d-120);
        else              src = p2e + p2[bl]*20 + (d-140);
        float4 av = *(const float4*)src;
        float4 wv = *(const float4*)(W + (size_t)(n0 + lrow) * 160 + k0 + lq * 4);
        As[lq*4+0][lrow] = av.x; As[lq*4+1][lrow] = av.y;
        As[lq*4+2][lrow] = av.z; As[lq*4+3][lrow] = av.w;
        Ws[lq*4+0][lrow] = wv.x; Ws[lq*4+1][lrow] = wv.y;
        Ws[lq*4+2][lrow] = wv.z; Ws[lq*4+3][lrow] = wv.w;
        __syncthreads();
        #pragma unroll
        for (int kk = 0; kk < 16; ++kk) {
            float a[4], w[4];
            #pragma unroll
            for (int e = 0; e < 4; ++e) { a[e] = As[kk][ty*4+e]; w[e] = Ws[kk][tx*4+e]; }
            #pragma unroll
            for (int i = 0; i < 4; ++i)
                #pragma unroll
                for (int j = 0; j < 4; ++j)
                    acc[i][j] += a[i] * w[j];
        }
        __syncthreads();
    }
    #pragma unroll
    for (int i = 0; i < 4; ++i) {
        int m = m0 + ty*4 + i;
        #pragma unroll
        for (int j = 0; j < 4; ++j) {
            int n = n0 + tx*4 + j;
            C[(size_t)m * 1024 + n] = acc[i][j] + bi[n] + bh[n];
        }
    }
}

// ---------------- K2a: per-replay reset (h slot 0 + flags) ----------------
__global__ void zero_kernel() {
    int idx = blockIdx.x * blockDim.x + threadIdx.x;   // 64 x 256 = 16384
    ((float4*)g_hbuf)[idx] = make_float4(0.f, 0.f, 0.f, 0.f);  // slot 0 = first 16384 float4
    if (blockIdx.x == 0 && threadIdx.x < 64)
        ((int4*)g_hflags)[threadIdx.x] = make_int4(0, 0, 0, 0);
}
__global__ void dummy_kernel() {}

// ---------------- K2: persistent BiLSTM with 16-block flag sync ----------------
// 256 blocks = 2 dir x 8 btile x 16 utile; group = 16 blocks sharing (dir,btile).
// Warp = 4b x 8u. w_t: [4g][64 k4][u pad17] f4; h_s: [16b][k4 pad69] f4.
#define WT_F4 (4*64*17)
#define HS_F4 (16*69)
#define LSTM_SMEM ((WT_F4 + HS_F4) * 16)

__global__ void __launch_bounds__(256, 2) lstm_kernel(
        const float* __restrict__ whh_f, const float* __restrict__ whh_b) {
    extern __shared__ float4 sm4[];
    float4* w_t = sm4;
    float4* h_s = sm4 + WT_F4;
    int blk = blockIdx.x;
    int dir = blk >> 7;
    int rem = blk & 127;
    int bt = rem >> 4;
    int ut = rem & 15;
    int gid = dir * 8 + bt;
    int b0 = bt * 16;
    int u0 = ut * 16;
    int tid = threadIdx.x;
    int ww = tid >> 5, lane = tid & 31;
    int b_local = (ww >> 1) * 4 + (lane >> 3);
    int u_local = (ww & 1) * 8 + (lane & 7);
    int b = b0 + b_local;
    int u = u0 + u_local;
    const float* whh = dir ? whh_b : whh_f;
    const float* xg  = dir ? g_xgb : g_xgf;
    float* xout      = dir ? g_xb  : g_xf;

    for (int x = tid; x < 4*64*16; x += 256) {
        int uu = x & 15;
        int k4 = (x >> 4) & 63;
        int g  = x >> 10;
        int R  = g*256 + u0 + uu;
        float4 v = *(const float4*)(whh + (size_t)R*256 + k4*4);
        w_t[(g*64 + k4)*17 + uu] = v;
    }
    __syncthreads();

    const float4* hrow = h_s + b_local*69;
    const float4* wp = w_t + u_local;

    int t0 = dir ? (LL-1) : 0;
    const float* xgp0 = xg + ((size_t)(b*LL + t0))*1024 + u;
    float xc0 = xgp0[0], xc1 = xgp0[256], xc2 = xgp0[512], xc3 = xgp0[768];

    float c_reg = 0.f;
    for (int s = 0; s < LL; ++s) {
        int t = dir ? (LL-1-s) : s;
        // wait for h[s] (slot s&3) from all peers; slot 0 pre-zeroed by zero_kernel
        if (s > 0) {
            if (tid < 16) {
                const int* fp = &g_hflags[gid][tid];
                int v;
                do {
                    asm volatile("ld.acquire.gpu.global.s32 %0, [%1];" : "=r"(v) : "l"(fp));
                } while (v < s);
            }
            __syncthreads();
        }
        // stage h tile (16b x 256u) from slot s&3 via L2
        const float4* hsrc = (const float4*)(g_hbuf + ((size_t)((s&3)*2 + dir)*BB + b0)*HID);
        for (int x = tid; x < 16*64; x += 256) {
            float4 v = __ldcg(hsrc + x);
            h_s[(x >> 6)*69 + (x & 63)] = v;
        }
        __syncthreads();

        float2 a0 = make_float2(0.f,0.f), a1 = make_float2(0.f,0.f);
        float2 a2 = make_float2(0.f,0.f), a3 = make_float2(0.f,0.f);
        #pragma unroll 8
        for (int k4 = 0; k4 < 64; ++k4) {
            float4 h4 = hrow[k4];
            float2 hA = make_float2(h4.x, h4.y);
            float2 hB = make_float2(h4.z, h4.w);
            float4 w;
            w = wp[(0*64 + k4)*17]; a0 = ffma2(hA, make_float2(w.x,w.y), a0); a0 = ffma2(hB, make_float2(w.z,w.w), a0);
            w = wp[(1*64 + k4)*17]; a1 = ffma2(hA, make_float2(w.x,w.y), a1); a1 = ffma2(hB, make_float2(w.z,w.w), a1);
            w = wp[(2*64 + k4)*17]; a2 = ffma2(hA, make_float2(w.x,w.y), a2); a2 = ffma2(hB, make_float2(w.z,w.w), a2);
            w = wp[(3*64 + k4)*17]; a3 = ffma2(hA, make_float2(w.x,w.y), a3); a3 = ffma2(hB, make_float2(w.z,w.w), a3);
        }
        float gi = xc0 + a0.x + a0.y;
        float gf = xc1 + a1.x + a1.y;
        float gg = xc2 + a2.x + a2.y;
        float go = xc3 + a3.x + a3.y;
        float ig = 1.f / (1.f + expf(-gi));
        float fg = 1.f / (1.f + expf(-gf));
        float gt = tanhf(gg);
        float og = 1.f / (1.f + expf(-go));
        c_reg = fg * c_reg + ig * gt;
        float h = og * tanhf(c_reg);
        // publish h[s+1] into slot (s+1)&3
        g_hbuf[((size_t)(((s+1)&3)*2 + dir)*BB + b)*HID + u] = h;
        xout[((size_t)(b*LL + t))*HID + u] = h;

        if (s + 1 < LL) {
            int tn = dir ? (LL-2-s) : (s+1);
            const float* xgp = xg + ((size_t)(b*LL + tn))*1024 + u;
            xc0 = xgp[0]; xc1 = xgp[256]; xc2 = xgp[512]; xc3 = xgp[768];
            __threadfence();
            __syncthreads();
            if (tid == 0) {
                int* fp = &g_hflags[gid][ut];
                int fv = s + 1;
                asm volatile("st.release.gpu.global.s32 [%0], %1;" :: "l"(fp), "r"(fv));
            }
        }
    }
}

// ---------------- K3: fused post, warp-per-l ----------------
__global__ void __launch_bounds__(256) post_kernel(const int* __restrict__ pos1,
                                                   const int* __restrict__ pos2) {
    int b = blockIdx.x;
    int tid = threadIdx.x;
    int w = tid >> 5, lane = tid & 31;
    __shared__ int e1s, e2s;
    __shared__ float he_s[256];
    __shared__ float lg[100];
    if (tid < 100) {
        if (pos1[b*100 + tid] == 68) e1s = tid;
        if (pos2[b*100 + tid] == 68) e2s = tid;
    }
    g_s[b*304 + tid] = 0.f;
    if (tid < 48) g_s[b*304 + 256 + tid] = 0.f;
    __syncthreads();
    {
        size_t r1 = (size_t)(b*100 + e1s)*256 + tid;
        size_t r2 = (size_t)(b*100 + e2s)*256 + tid;
        he_s[tid] = g_xf[r1] + g_xb[r1] + g_xf[r2] + g_xb[r2];
    }
    __syncthreads();

    for (int l = w; l < 100; l += 8) {
        size_t base = (size_t)(b*100 + l)*256 + lane*8;
        float4 f0 = *(const float4*)(g_xf + base);
        float4 f1 = *(const float4*)(g_xf + base + 4);
        float4 b0v = *(const float4*)(g_xb + base);
        float4 b1v = *(const float4*)(g_xb + base + 4);
        float xv[8];
        xv[0]=f0.x+b0v.x; xv[1]=f0.y+b0v.y; xv[2]=f0.z+b0v.z; xv[3]=f0.w+b0v.w;
        xv[4]=f1.x+b1v.x; xv[5]=f1.y+b1v.y; xv[6]=f1.z+b1v.z; xv[7]=f1.w+b1v.w;
        float sq = 0.f;
        #pragma unroll
        for (int j = 0; j < 8; ++j) sq += xv[j]*xv[j];
        float n2 = sq + __shfl_xor_sync(0xffffffffu, sq, 1);
        float sc = (n2 / (1.f + n2)) * rsqrtf(n2 + 1e-9f);
        float* up = g_u + (size_t)b*25600 + l*256 + lane*8;
        float4 o0 = make_float4(xv[0]*sc, xv[1]*sc, xv[2]*sc, xv[3]*sc);
        float4 o1 = make_float4(xv[4]*sc, xv[5]*sc, xv[6]*sc, xv[7]*sc);
        *(float4*)up = o0; *(float4*)(up+4) = o1;
        float pr = 0.f;
        #pragma unroll
        for (int j = 0; j < 8; ++j) pr += xv[j] * he_s[lane*8 + j];
        #pragma unroll
        for (int o2 = 16; o2; o2 >>= 1) pr += __shfl_xor_sync(0xffffffffu, pr, o2);
        if (lane == 0) lg[l] = pr;
    }
    __syncthreads();
    if (w == 0) {
        float mv = -1e30f;
        #pragma unroll
        for (int r = 0; r < 4; ++r) {
            int l = lane + r*32;
            if (l < 100) mv = fmaxf(mv, lg[l]);
        }
        #pragma unroll
        for (int o2 = 16; o2; o2 >>= 1) mv = fmaxf(mv, __shfl_xor_sync(0xffffffffu, mv, o2));
        float ssum = 0.f;
        #pragma unroll
        for (int r = 0; r < 4; ++r) {
            int l = lane + r*32;
            if (l < 100) ssum += expf(lg[l] - mv);
        }
        #pragma unroll
        for (int o2 = 16; o2; o2 >>= 1) ssum += __shfl_xor_sync(0xffffffffu, ssum, o2);
        #pragma unroll
        for (int r = 0; r < 4; ++r) {
            int l = lane + r*32;
            if (l < 100) g_att[b*100 + l] = expf(lg[l] - mv) / ssum;
        }
    }
}

// ---------------- K4: routing pass — class-aligned od ownership ----------------
// grid 256 = 32 ichunk x 8 bch; 320 threads. tid: bp = tid&7, q = tid>>3 (q<38 active).
// thread owns b in {2bp, 2bp+1}, od-pairs 4q..4q+3 (single class o = q>>1).
__global__ void __launch_bounds__(320) route_kernel(int first, int last,
        const float* __restrict__ broute, const float* __restrict__ Wc) {
    __shared__ float2 Wb[2][16*152];
    __shared__ float  u_s[2][16*17];
    __shared__ float  bbsm[16][20];
    __shared__ float  csm[16][20];

    int ichunk = blockIdx.x >> 3;
    int bch    = blockIdx.x & 7;
    int i0 = ichunk * 50;
    int tid = threadIdx.x;
    int bp = tid & 7;
    int q  = tid >> 3;           // 0..39
    bool act = q < 38;
    int qc = act ? q : 37;
    int o  = qc >> 1;
    int b0g = bch*16;

    // v in registers (passes 2,3)
    float2 vv[2][4];
    #pragma unroll
    for (int j = 0; j < 2; ++j)
        #pragma unroll
        for (int p = 0; p < 4; ++p) vv[j][p] = make_float2(0.f, 0.f);
    if (!first && act) {
        #pragma unroll
        for (int j = 0; j < 2; ++j)
            #pragma unroll
            for (int p = 0; p < 4; ++p)
                vv[j][p] = *(const float2*)&g_v[(b0g + 2*bp + j)*ODIM + 8*qc + 2*p];
    }

    // stage W[i0], u[i0]
    {
        const float4* src = (const float4*)(Wc + (size_t)i0 * 4864);
        float4* dst = (float4*)&Wb[0][0];
        for (int x = tid; x < 1216; x += 320) dst[x] = src[x];
        if (tid < 64) {
            int br = tid >> 2, c4 = (tid & 3) * 4;
            float4 uv = *(const float4*)&g_u[(size_t)(b0g + br)*25600 + i0*16 + c4];
            u_s[0][br*17 + c4 + 0] = uv.x; u_s[0][br*17 + c4 + 1] = uv.y;
            u_s[0][br*17 + c4 + 2] = uv.z; u_s[0][br*17 + c4 + 3] = uv.w;
        }
    }
    float2 sa[2][4];
    #pragma unroll
    for (int j = 0; j < 2; ++j)
        #pragma unroll
        for (int p = 0; p < 4; ++p) sa[j][p] = make_float2(0.f, 0.f);
    __syncthreads();

    for (int ii = 0; ii < 50; ++ii) {
        int i = i0 + ii;
        int cur = ii & 1, nxt = cur ^ 1;
        const float2* Wcur = &Wb[cur][0];
        const float*  Ucur = &u_s[cur][0];

        // register-prefetch next tiles
        float4 pf0, pf1, pf2, pf3, pfu;
        if (ii < 49) {
            const float4* src = (const float4*)(Wc + (size_t)(i+1) * 4864);
            pf0 = src[tid];
            pf1 = src[tid + 320];
            pf2 = src[tid + 640];
            if (tid + 960 < 1216) pf3 = src[tid + 960];
            if (tid < 64) {
                int br = tid >> 2, c4 = (tid & 3) * 4;
                pfu = *(const float4*)&g_u[(size_t)(b0g + br)*25600 + (i+1)*16 + c4];
            }
        }

        // u_hat: uh[j][p] over c
        float2 uh[2][4];
        #pragma unroll
        for (int j = 0; j < 2; ++j)
            #pragma unroll
            for (int p = 0; p < 4; ++p) uh[j][p] = make_float2(0.f, 0.f);
        #pragma unroll
        for (int c = 0; c < 16; ++c) {
            const float4* wrow = (const float4*)(Wcur + c*152 + 4*qc);
            float4 wA = wrow[0];            // od-pairs 4q, 4q+1
            float4 wB = wrow[1];            // od-pairs 4q+2, 4q+3
            float2 w0 = make_float2(wA.x, wA.y);
            float2 w1 = make_float2(wA.z, wA.w);
            float2 w2 = make_float2(wB.x, wB.y);
            float2 w3 = make_float2(wB.z, wB.w);
            float ua = Ucur[(2*bp + 0)*17 + c];
            float ub = Ucur[(2*bp + 1)*17 + c];
            float2 ua2 = make_float2(ua, ua);
            float2 ub2 = make_float2(ub, ub);
            uh[0][0] = ffma2(ua2, w0, uh[0][0]); uh[0][1] = ffma2(ua2, w1, uh[0][1]);
            uh[0][2] = ffma2(ua2, w2, uh[0][2]); uh[0][3] = ffma2(ua2, w3, uh[0][3]);
            uh[1][0] = ffma2(ub2, w0, uh[1][0]); uh[1][1] = ffma2(ub2, w1, uh[1][1]);
            uh[1][2] = ffma2(ub2, w2, uh[1][2]); uh[1][3] = ffma2(ub2, w3, uh[1][3]);
        }

        // agreement dot -> bbsm (classes complete via q^1 partner = lane^8)
        if (!first) {
            #pragma unroll
            for (int j = 0; j < 2; ++j) {
                float p = 0.f;
                #pragma unroll
                for (int pp = 0; pp < 4; ++pp)
                    p += uh[j][pp].x*vv[j][pp].x + uh[j][pp].y*vv[j][pp].y;
                p += __shfl_xor_sync(0xffffffffu, p, 8);
                if (act && (q & 1) == 0) bbsm[2*bp + j][o] = p;
            }
        }
        __syncthreads();

        // softmax per b (warps 0-7 handle 2 b each) + prefetch stores
        int warp = tid >> 5, lane = tid & 31;
        if (warp < 8) {
            #pragma unroll
            for (int rep = 0; rep < 2; ++rep) {
                int bsel = warp + rep*8;
                int bglob = b0g + bsel;
                float bbv = 0.f;
                if (lane < 19) {
                    if (first) bbv = broute[i*NCLS + lane];
                    else       bbv = g_bb[((size_t)bglob*NCAP + i)*NCLS + lane] + bbsm[bsel][lane];
                    if (!last) g_bb[((size_t)bglob*NCAP + i)*NCLS + lane] = bbv;
                }
                float val = (lane < 19) ? bbv : -1e30f;
                float m = val;
                #pragma unroll
                for (int o2 = 16; o2; o2 >>= 1) m = fmaxf(m, __shfl_xor_sync(0xffffffffu, m, o2));
                float e = (lane < 19) ? expf(val - m) : 0.f;
                float ssum = e;
                #pragma unroll
                for (int o2 = 16; o2; o2 >>= 1) ssum += __shfl_xor_sync(0xffffffffu, ssum, o2);
                float attv = g_att[bglob*LL + (i >> 4)];
                if (lane < 19) csm[bsel][lane] = (e / ssum) * attv;
            }
        }
        if (ii < 49) {
            float4* Wn = (float4*)&Wb[nxt][0];
            Wn[tid]       = pf0;
            Wn[tid + 320] = pf1;
            Wn[tid + 640] = pf2;
            if (tid + 960 < 1216) Wn[tid + 960] = pf3;
            if (tid < 64) {
                int br = tid >> 2, c4 = (tid & 3) * 4;
                u_s[nxt][br*17 + c4 + 0] = pfu.x; u_s[nxt][br*17 + c4 + 1] = pfu.y;
                u_s[nxt][br*17 + c4 + 2] = pfu.z; u_s[nxt][br*17 + c4 + 3] = pfu.w;
            }
        }
        __syncthreads();

        // s accumulate
        #pragma unroll
        for (int j = 0; j < 2; ++j) {
            float cc = csm[2*bp + j][o];
            float2 cc2 = make_float2(cc, cc);
            #pragma unroll
            for (int p = 0; p < 4; ++p)
                sa[j][p] = ffma2(cc2, uh[j][p], sa[j][p]);
        }
    }

    if (act) {
        #pragma unroll
        for (int j = 0; j < 2; ++j) {
            int brow = (b0g + 2*bp + j) * ODIM;
            #pragma unroll
            for (int p = 0; p < 4; ++p) {
                int od = 8*qc + 2*p;
                atomicAdd(&g_s[brow + od],     sa[j][p].x);
                atomicAdd(&g_s[brow + od + 1], sa[j][p].y);
            }
        }
    }
}

// ---------------- K5: v = squash(s), zero g_s, final lengths ----------------
__global__ void squash_v_kernel(float* __restrict__ out, int last) {
    int idx = blockIdx.x * blockDim.x + threadIdx.x;
    if (idx >= BB*NCLS) return;
    float* sp = g_s + (size_t)idx * 16;
    float4 a0 = *(const float4*)(sp + 0);
    float4 a1 = *(const float4*)(sp + 4);
    float4 a2 = *(const float4*)(sp + 8);
    float4 a3 = *(const float4*)(sp + 12);
    float n2 = a0.x*a0.x + a0.y*a0.y + a0.z*a0.z + a0.w*a0.w
             + a1.x*a1.x + a1.y*a1.y + a1.z*a1.z + a1.w*a1.w
             + a2.x*a2.x + a2.y*a2.y + a2.z*a2.z + a2.w*a2.w
             + a3.x*a3.x + a3.y*a3.y + a3.z*a3.z + a3.w*a3.w;
    float sc = (n2 / (1.f + n2)) * rsqrtf(n2 + 1e-9f);
    float* vp = g_v + (size_t)idx * 16;
    a0.x*=sc; a0.y*=sc; a0.z*=sc; a0.w*=sc;
    a1.x*=sc; a1.y*=sc; a1.z*=sc; a1.w*=sc;
    a2.x*=sc; a2.y*=sc; a2.z*=sc; a2.w*=sc;
    a3.x*=sc; a3.y*=sc; a3.z*=sc; a3.w*=sc;
    *(float4*)(vp + 0)  = a0; *(float4*)(vp + 4)  = a1;
    *(float4*)(vp + 8)  = a2; *(float4*)(vp + 12) = a3;
    float4 z = make_float4(0.f, 0.f, 0.f, 0.f);
    *(float4*)(sp + 0) = z; *(float4*)(sp + 4)  = z;
    *(float4*)(sp + 8) = z; *(float4*)(sp + 12) = z;
    if (last) out[idx] = sqrtf(n2 * sc * sc + 1e-9f);
}

// ---------------- launch ----------------
extern "C" void kernel_launch(void* const* d_in, const int* in_sizes, int n_in,
                              void* d_out, int out_size) {
    const int*   word   = (const int*)d_in[0];
    const int*   tag    = (const int*)d_in[1];
    const int*   pos1   = (const int*)d_in[2];
    const int*   pos2   = (const int*)d_in[3];
    const float* we     = (const float*)d_in[4];
    const float* te     = (const float*)d_in[5];
    const float* p1e    = (const float*)d_in[6];
    const float* p2e    = (const float*)d_in[7];
    const float* wihf   = (const float*)d_in[8];
    const float* whhf   = (const float*)d_in[9];
    const float* bihf   = (const float*)d_in[10];
    const float* bhhf   = (const float*)d_in[11];
    const float* wihb   = (const float*)d_in[12];
    const float* whhb   = (const float*)d_in[13];
    const float* bihb   = (const float*)d_in[14];
    const float* bhhb   = (const float*)d_in[15];
    const float* wcaps  = (const float*)d_in[16];
    const float* broute = (const float*)d_in[17];
    float* out = (float*)d_out;

    cudaFuncSetAttribute(lstm_kernel, cudaFuncAttributeMaxDynamicSharedMemorySize, LSTM_SMEM);

    dim3 gg(16, 200, 2);
    gemm_xg_kernel<<<gg, 256>>>(word, tag, pos1, pos2, we, te, p1e, p2e,
                                wihf, wihb, bihf, bhhf, bihb, bhhb);     // launch 1

    zero_kernel<<<64, 256>>>();                                          // launch 2 (reset flags + h slot0)
    dummy_kernel<<<1, 32>>>();                                           // launch 3

    lstm_kernel<<<256, 256, LSTM_SMEM>>>(whhf, whhb);                    // launch 4 = ncu slot

    post_kernel<<<BB, 256>>>(pos1, pos2);                                // launch 5

    for (int it = 0; it < 3; ++it) {
        route_kernel<<<256, 320>>>(it == 0 ? 1 : 0, it == 2 ? 1 : 0, broute, wcaps);
        squash_v_kernel<<<(BB*NCLS + 127)/128, 128>>>(out, it == 2 ? 1 : 0);
    }
    (void)in_sizes; (void)n_in; (void)out_size;
}